// round 7
// baseline (speedup 1.0000x reference)
#include <cuda_runtime.h>
#include <cuda_bf16.h>
#include <cstdint>

// Problem constants: B=4, C=T=16, n=1024, KS=3
// out = softmax_ch( cos_att * relu(x_gc_t + x) )

// ---------------- scratch (device globals) ----------------------------------
__device__ float g_XM[1024 * 2048];                        // GEMM result
__device__ float g_gc[4 * 1024 * 16 * 16];                 // [b][i][t][ch]
__device__ float g_cos[4 * 1024 * 16 * 16];                // [b][i][t][ch]
__device__ __align__(16) __nv_bfloat16 g_Ahi[1024 * 1024]; // x_tmp hi, K-major
__device__ __align__(16) __nv_bfloat16 g_Alo[1024 * 1024];
__device__ __align__(16) __nv_bfloat16 g_Bhi[2048 * 1024]; // Lk2^T hi, K-major
__device__ __align__(16) __nv_bfloat16 g_Blo[2048 * 1024];
__device__ __align__(16) __nv_bfloat16 g_Xbfh[64 * 1024 * 16]; // x[bc][i][t] hi
__device__ __align__(16) __nv_bfloat16 g_Xbfl[64 * 1024 * 16]; // lo
__device__ __align__(16) __nv_bfloat16 g_XTh[64 * 16 * 1024];  // x[bc][t][i] hi
__device__ __align__(16) __nv_bfloat16 g_XTl[64 * 16 * 1024];  // lo
__device__ float g_inorm[64 * 1024];                           // 1/||x_i||
__device__ __align__(16) float4 g_bperm[262144];               // beta, frag order

// ---------------- helpers ----------------------------------------------------
__device__ __forceinline__ uint32_t smem_u32(const void* p) {
    uint32_t a;
    asm("{ .reg .u64 t; cvta.to.shared.u64 t, %1; cvt.u32.u64 %0, t; }"
        : "=r"(a) : "l"(p));
    return a;
}
__device__ __forceinline__ void cp_async16(uint32_t dst, const void* src) {
    asm volatile("cp.async.cg.shared.global [%0], [%1], 16;" :: "r"(dst), "l"(src));
}
__device__ __forceinline__ void cp_commit() {
    asm volatile("cp.async.commit_group;" ::: "memory");
}
template <int N> __device__ __forceinline__ void cp_wait() {
    asm volatile("cp.async.wait_group %0;" :: "n"(N) : "memory");
}
__device__ __forceinline__ void mma16816(float* d, const uint32_t* a,
                                         const uint32_t* b) {
    asm volatile(
        "mma.sync.aligned.m16n8k16.row.col.f32.bf16.bf16.f32 "
        "{%0,%1,%2,%3}, {%4,%5,%6,%7}, {%8,%9}, {%0,%1,%2,%3};\n"
        : "+f"(d[0]), "+f"(d[1]), "+f"(d[2]), "+f"(d[3])
        : "r"(a[0]), "r"(a[1]), "r"(a[2]), "r"(a[3]), "r"(b[0]), "r"(b[1]));
}
__device__ __forceinline__ void ldsm_x4(uint32_t* r, uint32_t addr) {
    asm volatile("ldmatrix.sync.aligned.m8n8.x4.shared.b16 {%0,%1,%2,%3}, [%4];"
                 : "=r"(r[0]), "=r"(r[1]), "=r"(r[2]), "=r"(r[3]) : "r"(addr));
}
__device__ __forceinline__ uint32_t pack_bf16x2(float hi, float lo) {
    uint32_t r;
    asm("cvt.rn.satfinite.bf16x2.f32 %0, %1, %2;" : "=r"(r) : "f"(hi), "f"(lo));
    return r;
}
__device__ __forceinline__ float bf16lo_f(uint32_t u) {
    return __uint_as_float(u << 16);
}
__device__ __forceinline__ float bf16hi_f(uint32_t u) {
    return __uint_as_float(u & 0xFFFF0000u);
}
// sigmoid(z) = 0.5 * tanh(z/2) + 0.5  (1 MUFU)
__device__ __forceinline__ float sig_tanh(float z) {
    float t;
    asm("tanh.approx.f32 %0, %1;" : "=f"(t) : "f"(0.5f * z));
    return fmaf(0.5f, t, 0.5f);
}

// =============================================================================
// P1: x -> (a) g_Ahi/lo, (b) g_Xbfh/l + g_inorm, (c) g_XTh/l
// =============================================================================
__global__ __launch_bounds__(256) void p1_convA(const float* __restrict__ x)
{
    __shared__ float s[16][258];
    const int g = blockIdx.x;          // 0..63 = bc
    const int tid = threadIdx.x;
    for (int c = 0; c < 4; c++) {
        __syncthreads();
#pragma unroll
        for (int it = 0; it < 16; it++) {
            int idx = tid + it * 256;                 // i_local*16 + t
            float v = x[g * 16384 + c * 4096 + idx];
            s[idx & 15][idx >> 4] = v;
        }
        __syncthreads();
        {   // (a)
            const int rl = tid >> 4;
            const int kk0 = (tid & 15) * 16;
            alignas(16) __nv_bfloat16 hb[16], lb[16];
#pragma unroll
            for (int q = 0; q < 16; q++) {
                float v = s[rl][kk0 + q];
                __nv_bfloat16 h = __float2bfloat16(v);
                hb[q] = h;
                lb[q] = __float2bfloat16(v - __bfloat162float(h));
            }
            size_t off = (size_t)(g * 16 + rl) * 1024 + c * 256 + kk0;
            *(uint4*)(g_Ahi + off)     = *(uint4*)(hb);
            *(uint4*)(g_Ahi + off + 8) = *(uint4*)(hb + 8);
            *(uint4*)(g_Alo + off)     = *(uint4*)(lb);
            *(uint4*)(g_Alo + off + 8) = *(uint4*)(lb + 8);
        }
        {   // (b)
            const int i = c * 256 + tid;
            alignas(16) __nv_bfloat16 hb[16], lb[16];
            float s2 = 0.f;
#pragma unroll
            for (int t = 0; t < 16; t++) {
                float v = s[t][tid];
                s2 = fmaf(v, v, s2);
                __nv_bfloat16 h = __float2bfloat16(v);
                hb[t] = h;
                lb[t] = __float2bfloat16(v - __bfloat162float(h));
            }
            g_inorm[g * 1024 + i] = rsqrtf(s2);
            size_t off = (size_t)(g * 1024 + i) * 16;
            *(uint4*)(g_Xbfh + off)     = *(uint4*)(hb);
            *(uint4*)(g_Xbfh + off + 8) = *(uint4*)(hb + 8);
            *(uint4*)(g_Xbfl + off)     = *(uint4*)(lb);
            *(uint4*)(g_Xbfl + off + 8) = *(uint4*)(lb + 8);
        }
        {   // (c)
            const int t = tid >> 4;
            const int ib = (tid & 15) * 16;
            alignas(16) __nv_bfloat16 hb[16], lb[16];
#pragma unroll
            for (int q = 0; q < 16; q++) {
                float v = s[t][ib + q];
                __nv_bfloat16 h = __float2bfloat16(v);
                hb[q] = h;
                lb[q] = __float2bfloat16(v - __bfloat162float(h));
            }
            size_t off = (size_t)(g * 16 + t) * 1024 + c * 256 + ib;
            *(uint4*)(g_XTh + off)     = *(uint4*)(hb);
            *(uint4*)(g_XTh + off + 8) = *(uint4*)(hb + 8);
            *(uint4*)(g_XTl + off)     = *(uint4*)(lb);
            *(uint4*)(g_XTl + off + 8) = *(uint4*)(lb + 8);
        }
    }
}

// =============================================================================
// P2: Lk2 transpose -> B_hi/B_lo.
// =============================================================================
__global__ __launch_bounds__(256) void p2_convB(const float* __restrict__ Lk)
{
    __shared__ float s[32][33];
    const int jt = blockIdx.x;
    const int kt = blockIdx.y;
    const int tx = threadIdx.x & 31, ty = threadIdx.x >> 5;
#pragma unroll
    for (int p = 0; p < 4; p++) {
        int ky = ty + p * 8;
        s[tx][ky] = Lk[(kt * 32 + ky) * 3072 + 1024 + jt * 32 + tx];
    }
    __syncthreads();
#pragma unroll
    for (int p = 0; p < 4; p++) {
        int jy = ty + p * 8;
        float v = s[jy][tx];
        __nv_bfloat16 h = __float2bfloat16(v);
        size_t off = (size_t)(jt * 32 + jy) * 1024 + kt * 32 + tx;
        g_Bhi[off] = h;
        g_Blo[off] = __float2bfloat16(v - __bfloat162float(h));
    }
}

// =============================================================================
// P3: beta -> fragment-ordered g_bperm.
// =============================================================================
__global__ __launch_bounds__(256) void p3_permBeta(const float* __restrict__ beta)
{
    const int idx = blockIdx.x * 256 + threadIdx.x;    // 0..131071
    const int lane = idx & 31;
    const int js = (idx >> 5) & 63;
    const int ib = idx >> 11;
    const int g = lane >> 2, tg = lane & 3;
    const int r0 = ib * 16 + g, r1 = r0 + 8;
    const int c0 = js * 16 + 2 * tg, c1 = c0 + 8;
    const float* b0 = beta + (size_t)r0 * 1024;
    const float* b1 = beta + (size_t)r1 * 1024;
    float2 a0 = *(const float2*)(b0 + c0);
    float2 a1 = *(const float2*)(b0 + c1);
    float2 a2 = *(const float2*)(b1 + c0);
    float2 a3 = *(const float2*)(b1 + c1);
    g_bperm[idx * 2]     = make_float4(a0.x, a0.y, a1.x, a1.y);
    g_bperm[idx * 2 + 1] = make_float4(a2.x, a2.y, a3.x, a3.y);
}

// =============================================================================
// K1: split-bf16 HMMA GEMM, 64x128 CTA tile for 2 CTA/SM occupancy.
// grid(16 coltiles, 16 rowtiles) = 256 CTAs, 256 thr (8 warps = 4m x 2n),
// warp tile 16m x 64n. 3-stage cp.async (12KB/stage), 1 sync/kt.
// =============================================================================
__global__ __launch_bounds__(256, 2) void k1_mma()
{
    // stage layout: Ahi[0,2048) Alo[2048,4096) Bhi[4096,8192) Blo[8192,12288)
    __shared__ __align__(16) uint8_t smem[3][12288];

    const int tid = threadIdx.x;
    const int wid = tid >> 5, lane = tid & 31;
    const int g = lane >> 2, tg = lane & 3;
    const int wm = (wid & 3) * 16;       // 4 m-warps
    const int wn = (wid >> 2) * 64;      // 2 n-warps
    const int row0 = blockIdx.y * 64;
    const int col0 = blockIdx.x * 128;

    const __nv_bfloat16* Asrc_h = g_Ahi + (size_t)row0 * 1024;
    const __nv_bfloat16* Asrc_l = g_Alo + (size_t)row0 * 1024;
    const __nv_bfloat16* Bsrc_h = g_Bhi + (size_t)col0 * 1024;
    const __nv_bfloat16* Bsrc_l = g_Blo + (size_t)col0 * 1024;

    float acc[8][4];
#pragma unroll
    for (int nt = 0; nt < 8; nt++)
#pragma unroll
        for (int q = 0; q < 4; q++) acc[nt][q] = 0.f;

    auto load_stage = [&](int s, int kt) {
#pragma unroll
        for (int q = 0; q < 3; q++) {
            int idx = tid + q * 256;          // 0..767
            const __nv_bfloat16* src;
            uint32_t arr_off;
            int rc;
            if (idx < 256) {                  // A: 64 rows x 2 chunks, hi|lo
                rc = idx & 127;
                src = (idx < 128) ? Asrc_h : Asrc_l;
                arr_off = (idx < 128) ? 0 : 2048;
            } else {                          // B: 128 rows x 2 chunks, hi|lo
                rc = (idx - 256) & 255;
                src = (idx < 512) ? Bsrc_h : Bsrc_l;
                arr_off = (idx < 512) ? 4096 : 8192;
            }
            int r = rc >> 1, c = rc & 1;
            uint32_t dst = smem_u32(&smem[s][0]) + arr_off + r * 32 +
                           ((c * 16) ^ (((r >> 2) & 1) << 4));
            cp_async16(dst, src + (size_t)r * 1024 + kt * 16 + c * 8);
        }
        cp_commit();
    };

    // ldmatrix per-lane offsets
    uint32_t offA, offB[4];
    {
        int arow = ((lane >> 3) & 1) * 8 + (lane & 7);
        int cA = lane >> 4;
        int brow = ((lane >> 4) << 3) + (lane & 7);
        int cB = (lane >> 3) & 1;
        int rA = wm + arow;
        offA = rA * 32 + ((cA ^ ((rA >> 2) & 1)) << 4);
#pragma unroll
        for (int p = 0; p < 4; p++) {
            int r = wn + p * 16 + brow;
            offB[p] = r * 32 + ((cB ^ ((r >> 2) & 1)) << 4);
        }
    }

    load_stage(0, 0);
    load_stage(1, 1);

    int sread = 0;
    for (int kt = 0; kt < 64; kt++) {
        if (kt < 63) cp_wait<1>(); else cp_wait<0>();
        __syncthreads();
        if (kt + 2 < 64) {
            int sw = sread + 2; if (sw >= 3) sw -= 3;
            load_stage(sw, kt + 2);
        }

        const uint32_t base = smem_u32(&smem[sread][0]);

        uint32_t ah[4], al[4], bh[4][4], bl[4][4];
        ldsm_x4(ah, base + offA);
        ldsm_x4(al, base + 2048 + offA);
#pragma unroll
        for (int p = 0; p < 4; p++) {
            ldsm_x4(bh[p], base + 4096 + offB[p]);
            ldsm_x4(bl[p], base + 8192 + offB[p]);
        }

#pragma unroll
        for (int nt = 0; nt < 8; nt++) {
            const uint32_t* bhw = &bh[nt >> 1][(nt & 1) * 2];
            const uint32_t* blw = &bl[nt >> 1][(nt & 1) * 2];
            mma16816(acc[nt], ah, bhw);
            mma16816(acc[nt], ah, blw);
            mma16816(acc[nt], al, bhw);
        }
        sread = (sread + 1 == 3) ? 0 : sread + 1;
    }
#pragma unroll
    for (int nt = 0; nt < 8; nt++) {
        int r = row0 + wm + g;
        int c = col0 + wn + nt * 8 + tg * 2;
        *(float2*)&g_XM[(size_t)r * 2048 + c] =
            make_float2(acc[nt][0], acc[nt][1]);
        *(float2*)&g_XM[(size_t)(r + 8) * 2048 + c] =
            make_float2(acc[nt][2], acc[nt][3]);
    }
}

// =============================================================================
// K2: fold theta
// =============================================================================
__global__ __launch_bounds__(256) void k2_fold(const float* __restrict__ x,
                                               const float* __restrict__ theta,
                                               const float* __restrict__ bias)
{
    __shared__ float th[768];
    __shared__ float bs[16];
    const int tid = threadIdx.x;
    for (int q = tid; q < 768; q += 256) th[q] = theta[q];
    if (tid < 16) bs[tid] = bias[tid];
    __syncthreads();

    const int idx = blockIdx.x * 256 + tid;
    const int i   = idx & 1023;
    const int tau = (idx >> 10) & 15;
    const int b   = idx >> 14;

    const float* xr = x + (((b << 4) + tau) << 14) + (i << 4);
    float xrow[16];
#pragma unroll
    for (int q = 0; q < 4; q++)
        *(float4*)(xrow + 4 * q) = *(const float4*)(xr + 4 * q);

    float acc[16];
#pragma unroll
    for (int c = 0; c < 16; c++) acc[c] = bs[c];

    const int rbase = (b << 8) + (tau << 4);
#pragma unroll 4
    for (int tp = 0; tp < 16; ++tp) {
        const float* xm = g_XM + (size_t)(rbase + tp) * 2048 + i;
        float a0 = xrow[tp];
        float a1 = xm[0];
        float a2 = xm[1024];
        const float* t0 = th + tp * 48;
#pragma unroll
        for (int c = 0; c < 16; c++)
            acc[c] += a0 * t0[c] + a1 * t0[16 + c] + a2 * t0[32 + c];
    }

    float* dst = g_gc + ((size_t)b << 18) + (i << 8) + (tau << 4);
#pragma unroll
    for (int q = 0; q < 4; q++)
        *(float4*)(dst + 4 * q) = *(float4*)(acc + 4 * q);
}

// =============================================================================
// K3T: tensorized attention (unchanged from R6-passing version).
// =============================================================================
__global__ __launch_bounds__(256) void k3t()
{
    __shared__ __align__(16) uint8_t sb[2][4][4096]; // [stage][Xjh,Xjl,XTh,XTl]
    __shared__ float sInj[1024];

    const int tid  = threadIdx.x;
    const int lane = tid & 31, wid = tid >> 5;
    const int g = lane >> 2, tg = lane & 3;
    const int bc = blockIdx.y;
    const int i0 = blockIdx.x * 256;
    const int b  = bc >> 4, ch = bc & 15;

    for (int q = tid; q < 1024; q += 256) sInj[q] = g_inorm[bc * 1024 + q];

    const int rw = i0 + wid * 32;
    const int ib0 = rw >> 4;

    uint32_t aih[2][4], ail[2][4];
    float nia[2], nib[2];
#pragma unroll
    for (int p = 0; p < 2; p++) {
        const int r = rw + 16 * p + g;
        const uint32_t* Xh = (const uint32_t*)(g_Xbfh + ((size_t)bc * 1024 + r) * 16);
        const uint32_t* Xl = (const uint32_t*)(g_Xbfl + ((size_t)bc * 1024 + r) * 16);
        aih[p][0] = Xh[tg];      aih[p][1] = Xh[64 + tg];
        aih[p][2] = Xh[tg + 4];  aih[p][3] = Xh[64 + tg + 4];
        ail[p][0] = Xl[tg];      ail[p][1] = Xl[64 + tg];
        ail[p][2] = Xl[tg + 4];  ail[p][3] = Xl[64 + tg + 4];
        nia[p] = g_inorm[bc * 1024 + r];
        nib[p] = g_inorm[bc * 1024 + r + 8];
    }

    float o[2][2][4];
#pragma unroll
    for (int p = 0; p < 2; p++)
#pragma unroll
        for (int u = 0; u < 2; u++)
#pragma unroll
            for (int q = 0; q < 4; q++) o[p][u][q] = 0.f;

    const int jr = ((lane >> 4) << 3) + (lane & 7);
    const int cS = (lane >> 3) & 1;
    const uint32_t offS = (uint32_t)(jr * 32 + ((cS ^ ((jr >> 2) & 1)) << 4));
    const int tl = jr;
    const int cbit = (lane >> 3) & 1;

    auto stage = [&](int st, int jt) {
        const size_t xb = ((size_t)bc * 1024 + jt * 128) * 32;   // bytes
        const size_t tb = ((size_t)bc * 16384 + jt * 128) * 2;   // bytes
        const char* srcs[4] = {(const char*)g_Xbfh + xb, (const char*)g_Xbfl + xb,
                               (const char*)g_XTh + tb,  (const char*)g_XTl + tb};
#pragma unroll
        for (int a = 0; a < 4; a++) {
            int q = tid;
            uint32_t dst;
            const char* src;
            if (a < 2) {
                int j = q >> 1, c = q & 1;
                dst = (uint32_t)(j * 32 + ((c ^ ((j >> 2) & 1)) << 4));
                src = srcs[a] + (size_t)j * 32 + c * 16;
            } else {
                int t = q >> 4, c = q & 15;
                dst = (uint32_t)(t * 256 + ((c ^ t) << 4));
                src = srcs[a] + (size_t)t * 2048 + c * 16;
            }
            cp_async16(smem_u32(&sb[st][a][0]) + dst, src);
        }
        cp_commit();
    };

    __syncthreads();            // sInj ready
    stage(0, 0);

    for (int jt = 0; jt < 8; jt++) {
        cp_wait<0>();
        __syncthreads();
        if (jt < 7) stage((jt + 1) & 1, jt + 1);

        const uint32_t sbase = smem_u32(&sb[jt & 1][0][0]);

#pragma unroll 2
        for (int s2 = 0; s2 < 8; s2++) {
            const int js = s2 * 16;
            const int jabs = jt * 128 + js;
            const int jstep = jt * 8 + s2;

            uint32_t bh4[4], bl4[4];
            ldsm_x4(bh4, sbase + js * 32 + offS);
            ldsm_x4(bl4, sbase + 4096 + js * 32 + offS);
            const uint32_t cj = 2 * s2 + cbit;
            const uint32_t offP = (uint32_t)(tl * 256 + ((cj ^ tl) << 4));
            uint32_t th4[4], tl4[4];
            ldsm_x4(th4, sbase + 2 * 4096 + offP);
            ldsm_x4(tl4, sbase + 3 * 4096 + offP);

            float2 nj0 = *(const float2*)&sInj[jabs + 2 * tg];
            float2 nj1 = *(const float2*)&sInj[jabs + 8 + 2 * tg];

#pragma unroll
            for (int p = 0; p < 2; p++) {
                const float4* bp =
                    g_bperm + (((size_t)(ib0 + p) * 64 + jstep) * 32 + lane) * 2;
                float4 v0 = bp[0];
                float4 v1 = bp[1];

                float s0[4] = {0.f, 0.f, 0.f, 0.f};
                float s1[4] = {0.f, 0.f, 0.f, 0.f};
                mma16816(s0, aih[p], &bh4[0]); mma16816(s0, aih[p], &bl4[0]);
                mma16816(s0, ail[p], &bh4[0]);
                mma16816(s1, aih[p], &bh4[2]); mma16816(s1, aih[p], &bl4[2]);
                mma16816(s1, ail[p], &bh4[2]);

                float p00 = sig_tanh(v0.x * s0[0] * nia[p] * nj0.x);
                float p01 = sig_tanh(v0.y * s0[1] * nia[p] * nj0.y);
                float p02 = sig_tanh(v1.x * s0[2] * nib[p] * nj0.x);
                float p03 = sig_tanh(v1.y * s0[3] * nib[p] * nj0.y);
                float p10 = sig_tanh(v0.z * s1[0] * nia[p] * nj1.x);
                float p11 = sig_tanh(v0.w * s1[1] * nia[p] * nj1.y);
                float p12 = sig_tanh(v1.z * s1[2] * nib[p] * nj1.x);
                float p13 = sig_tanh(v1.w * s1[3] * nib[p] * nj1.y);

                uint32_t pah[4], pal[4];
                pah[0] = pack_bf16x2(p01, p00);
                pah[1] = pack_bf16x2(p03, p02);
                pah[2] = pack_bf16x2(p11, p10);
                pah[3] = pack_bf16x2(p13, p12);
                pal[0] = pack_bf16x2(p01 - bf16hi_f(pah[0]), p00 - bf16lo_f(pah[0]));
                pal[1] = pack_bf16x2(p03 - bf16hi_f(pah[1]), p02 - bf16lo_f(pah[1]));
                pal[2] = pack_bf16x2(p11 - bf16hi_f(pah[2]), p10 - bf16lo_f(pah[2]));
                pal[3] = pack_bf16x2(p13 - bf16hi_f(pah[3]), p12 - bf16lo_f(pah[3]));

                mma16816(o[p][0], pah, &th4[0]); mma16816(o[p][0], pah, &tl4[0]);
                mma16816(o[p][0], pal, &th4[0]);
                mma16816(o[p][1], pah, &th4[2]); mma16816(o[p][1], pah, &tl4[2]);
                mma16816(o[p][1], pal, &th4[2]);
            }
        }
    }

#pragma unroll
    for (int p = 0; p < 2; p++) {
        const int r = rw + 16 * p + g;
        float* base = g_cos + (((size_t)(b * 1024 + r) * 16) * 16) + ch;
        base[(2 * tg) * 16]            = o[p][0][0];
        base[(2 * tg + 1) * 16]        = o[p][0][1];
        base[2048 + (2 * tg) * 16]     = o[p][0][2];
        base[2048 + (2 * tg + 1) * 16] = o[p][0][3];
        base[(8 + 2 * tg) * 16]            = o[p][1][0];
        base[(8 + 2 * tg + 1) * 16]        = o[p][1][1];
        base[2048 + (8 + 2 * tg) * 16]     = o[p][1][2];
        base[2048 + (8 + 2 * tg + 1) * 16] = o[p][1][3];
    }
}

// =============================================================================
// K4: fuse + channel softmax
// =============================================================================
__global__ __launch_bounds__(256) void k4_final(const float* __restrict__ x,
                                                float* __restrict__ out)
{
    const int idx = blockIdx.x * 256 + threadIdx.x;
    const int t = idx & 15;
    const int i = (idx >> 4) & 1023;
    const int b = idx >> 14;

    const float* gc = g_gc + (size_t)idx * 16;
    const float* cs = g_cos + (size_t)idx * 16;

    float g[16];
#pragma unroll
    for (int c = 0; c < 16; c++) {
        float xv = x[(((b << 4) + c) << 14) + (i << 4) + t];
        float r = gc[c] + xv;
        r = r > 0.f ? r : 0.f;
        g[c] = cs[c] * r;
    }
    float m = g[0];
#pragma unroll
    for (int c = 1; c < 16; c++) m = fmaxf(m, g[c]);
    float s = 0.f;
#pragma unroll
    for (int c = 0; c < 16; c++) {
        float e = __expf(g[c] - m);
        g[c] = e;
        s += e;
    }
    float rs = __fdividef(1.f, s);
#pragma unroll
    for (int c = 0; c < 16; c++)
        out[(((b << 4) + c) << 14) + (i << 4) + t] = g[c] * rs;
}

// =============================================================================
extern "C" void kernel_launch(void* const* d_in, const int* in_sizes, int n_in,
                              void* d_out, int out_size)
{
    const float* x     = (const float*)d_in[0];
    const float* beta  = (const float*)d_in[1];
    const float* theta = (const float*)d_in[2];
    const float* bias  = (const float*)d_in[3];
    const float* Lk    = (const float*)d_in[4];
    float* out = (float*)d_out;

    p1_convA<<<64, 256>>>(x);
    p2_convB<<<dim3(64, 32), 256>>>(Lk);
    p3_permBeta<<<512, 256>>>(beta);
    k1_mma<<<dim3(16, 16), 256>>>();
    k3t<<<dim3(4, 64), 256>>>();
    k2_fold<<<256, 256>>>(x, theta, bias);
    k4_final<<<256, 256>>>(x, out);
}

// round 8
// speedup vs baseline: 1.1768x; 1.1768x over previous
#include <cuda_runtime.h>
#include <cuda_bf16.h>
#include <cstdint>

// Problem constants: B=4, C=T=16, n=1024, KS=3
// out = softmax_ch( cos_att * relu(x_gc_t + x) )

// ---------------- scratch (device globals) ----------------------------------
__device__ float g_XM[1024 * 2048];                        // GEMM result
__device__ float g_gc[4 * 1024 * 16 * 16];                 // [b][i][t][ch]
__device__ float g_cos[4 * 1024 * 16 * 16];                // [b][i][t][ch]
__device__ __align__(16) __nv_bfloat16 g_Ahi[1024 * 1024]; // x_tmp hi, K-major
__device__ __align__(16) __nv_bfloat16 g_Alo[1024 * 1024];
__device__ __align__(16) __nv_bfloat16 g_Bhi[2048 * 1024]; // Lk2^T hi, K-major
__device__ __align__(16) __nv_bfloat16 g_Blo[2048 * 1024];
__device__ __align__(16) __nv_bfloat16 g_Xbfh[64 * 1024 * 16]; // x[bc][i][t] hi
__device__ __align__(16) __nv_bfloat16 g_Xbfl[64 * 1024 * 16]; // lo
__device__ __align__(16) __nv_bfloat16 g_XTh[64 * 16 * 1024];  // x[bc][t][i] hi
__device__ __align__(16) __nv_bfloat16 g_XTl[64 * 16 * 1024];  // lo
__device__ float g_inorm[64 * 1024];                           // 1/||x_i||
__device__ __align__(16) float4 g_bperm[262144];               // beta, frag order

// ---------------- helpers ----------------------------------------------------
__device__ __forceinline__ uint32_t smem_u32(const void* p) {
    uint32_t a;
    asm("{ .reg .u64 t; cvta.to.shared.u64 t, %1; cvt.u32.u64 %0, t; }"
        : "=r"(a) : "l"(p));
    return a;
}
__device__ __forceinline__ void cp_async16(uint32_t dst, const void* src) {
    asm volatile("cp.async.cg.shared.global [%0], [%1], 16;" :: "r"(dst), "l"(src));
}
__device__ __forceinline__ void cp_commit() {
    asm volatile("cp.async.commit_group;" ::: "memory");
}
template <int N> __device__ __forceinline__ void cp_wait() {
    asm volatile("cp.async.wait_group %0;" :: "n"(N) : "memory");
}
__device__ __forceinline__ void mma16816(float* d, const uint32_t* a,
                                         const uint32_t* b) {
    asm volatile(
        "mma.sync.aligned.m16n8k16.row.col.f32.bf16.bf16.f32 "
        "{%0,%1,%2,%3}, {%4,%5,%6,%7}, {%8,%9}, {%0,%1,%2,%3};\n"
        : "+f"(d[0]), "+f"(d[1]), "+f"(d[2]), "+f"(d[3])
        : "r"(a[0]), "r"(a[1]), "r"(a[2]), "r"(a[3]), "r"(b[0]), "r"(b[1]));
}
__device__ __forceinline__ void ldsm_x4(uint32_t* r, uint32_t addr) {
    asm volatile("ldmatrix.sync.aligned.m8n8.x4.shared.b16 {%0,%1,%2,%3}, [%4];"
                 : "=r"(r[0]), "=r"(r[1]), "=r"(r[2]), "=r"(r[3]) : "r"(addr));
}
__device__ __forceinline__ uint32_t pack_bf16x2(float hi, float lo) {
    uint32_t r;
    asm("cvt.rn.satfinite.bf16x2.f32 %0, %1, %2;" : "=r"(r) : "f"(hi), "f"(lo));
    return r;
}
__device__ __forceinline__ float bf16lo_f(uint32_t u) {
    return __uint_as_float(u << 16);
}
__device__ __forceinline__ float bf16hi_f(uint32_t u) {
    return __uint_as_float(u & 0xFFFF0000u);
}
// sigmoid(z) = 0.5 * tanh(z/2) + 0.5  (1 MUFU)
__device__ __forceinline__ float sig_tanh(float z) {
    float t;
    asm("tanh.approx.f32 %0, %1;" : "=f"(t) : "f"(0.5f * z));
    return fmaf(0.5f, t, 0.5f);
}

// =============================================================================
// Prepass bodies
// =============================================================================
__device__ __forceinline__ void p1_body(uint8_t* spre, const float* __restrict__ x,
                                        int g)
{
    float (*s)[258] = (float(*)[258])spre;
    const int tid = threadIdx.x;
    for (int c = 0; c < 4; c++) {
        __syncthreads();
#pragma unroll
        for (int it = 0; it < 16; it++) {
            int idx = tid + it * 256;                 // i_local*16 + t
            float v = x[g * 16384 + c * 4096 + idx];
            s[idx & 15][idx >> 4] = v;
        }
        __syncthreads();
        {   // (a) A matrices: row = g*16 + t, cols i
            const int rl = tid >> 4;
            const int kk0 = (tid & 15) * 16;
            alignas(16) __nv_bfloat16 hb[16], lb[16];
#pragma unroll
            for (int q = 0; q < 16; q++) {
                float v = s[rl][kk0 + q];
                __nv_bfloat16 h = __float2bfloat16(v);
                hb[q] = h;
                lb[q] = __float2bfloat16(v - __bfloat162float(h));
            }
            size_t off = (size_t)(g * 16 + rl) * 1024 + c * 256 + kk0;
            *(uint4*)(g_Ahi + off)     = *(uint4*)(hb);
            *(uint4*)(g_Ahi + off + 8) = *(uint4*)(hb + 8);
            *(uint4*)(g_Alo + off)     = *(uint4*)(lb);
            *(uint4*)(g_Alo + off + 8) = *(uint4*)(lb + 8);
        }
        {   // (b) Xbf rows + inv norm
            const int i = c * 256 + tid;
            alignas(16) __nv_bfloat16 hb[16], lb[16];
            float s2 = 0.f;
#pragma unroll
            for (int t = 0; t < 16; t++) {
                float v = s[t][tid];
                s2 = fmaf(v, v, s2);
                __nv_bfloat16 h = __float2bfloat16(v);
                hb[t] = h;
                lb[t] = __float2bfloat16(v - __bfloat162float(h));
            }
            g_inorm[g * 1024 + i] = rsqrtf(s2);
            size_t off = (size_t)(g * 1024 + i) * 16;
            *(uint4*)(g_Xbfh + off)     = *(uint4*)(hb);
            *(uint4*)(g_Xbfh + off + 8) = *(uint4*)(hb + 8);
            *(uint4*)(g_Xbfl + off)     = *(uint4*)(lb);
            *(uint4*)(g_Xbfl + off + 8) = *(uint4*)(lb + 8);
        }
        {   // (c) XT rows
            const int t = tid >> 4;
            const int ib = (tid & 15) * 16;
            alignas(16) __nv_bfloat16 hb[16], lb[16];
#pragma unroll
            for (int q = 0; q < 16; q++) {
                float v = s[t][ib + q];
                __nv_bfloat16 h = __float2bfloat16(v);
                hb[q] = h;
                lb[q] = __float2bfloat16(v - __bfloat162float(h));
            }
            size_t off = (size_t)(g * 16 + t) * 1024 + c * 256 + ib;
            *(uint4*)(g_XTh + off)     = *(uint4*)(hb);
            *(uint4*)(g_XTh + off + 8) = *(uint4*)(hb + 8);
            *(uint4*)(g_XTl + off)     = *(uint4*)(lb);
            *(uint4*)(g_XTl + off + 8) = *(uint4*)(lb + 8);
        }
    }
}

__device__ __forceinline__ void p2_body(uint8_t* spre, const float* __restrict__ Lk,
                                        int jt, int kt)
{
    float (*s)[33] = (float(*)[33])spre;
    const int tx = threadIdx.x & 31, ty = threadIdx.x >> 5;
#pragma unroll
    for (int p = 0; p < 4; p++) {
        int ky = ty + p * 8;
        s[tx][ky] = Lk[(kt * 32 + ky) * 3072 + 1024 + jt * 32 + tx];
    }
    __syncthreads();
#pragma unroll
    for (int p = 0; p < 4; p++) {
        int jy = ty + p * 8;
        float v = s[jy][tx];
        __nv_bfloat16 h = __float2bfloat16(v);
        size_t off = (size_t)(jt * 32 + jy) * 1024 + kt * 32 + tx;
        g_Bhi[off] = h;
        g_Blo[off] = __float2bfloat16(v - __bfloat162float(h));
    }
}

__device__ __forceinline__ void p3_body(const float* __restrict__ beta, int blk)
{
    const int idx = blk * 256 + threadIdx.x;    // 0..131071
    const int lane = idx & 31;
    const int js = (idx >> 5) & 63;
    const int ib = idx >> 11;
    const int g = lane >> 2, tg = lane & 3;
    const int r0 = ib * 16 + g, r1 = r0 + 8;
    const int c0 = js * 16 + 2 * tg, c1 = c0 + 8;
    const float* b0 = beta + (size_t)r0 * 1024;
    const float* b1 = beta + (size_t)r1 * 1024;
    float2 a0 = *(const float2*)(b0 + c0);
    float2 a1 = *(const float2*)(b0 + c1);
    float2 a2 = *(const float2*)(b1 + c0);
    float2 a3 = *(const float2*)(b1 + c1);
    g_bperm[idx * 2]     = make_float4(a0.x, a0.y, a1.x, a1.y);
    g_bperm[idx * 2 + 1] = make_float4(a2.x, a2.y, a3.x, a3.y);
}

__global__ __launch_bounds__(256) void k_pre(const float* __restrict__ x,
                                             const float* __restrict__ Lk,
                                             const float* __restrict__ beta)
{
    __shared__ __align__(16) uint8_t spre[16512];
    const int bid = blockIdx.x;
    if (bid < 64) p1_body(spre, x, bid);
    else if (bid < 2112) p2_body(spre, Lk, (bid - 64) & 63, (bid - 64) >> 6);
    else p3_body(beta, bid - 2112);
}

// =============================================================================
// Heavy fused kernel: even blocks = k1 GEMM tile, odd blocks = k3t attention.
// Both use 36864 B of overlaid static smem, 256 threads.
// =============================================================================
__device__ __forceinline__ void k1_body(uint8_t* sm, int bid)
{
    // stage s at sm + s*12288: Ahi[0) Alo[2048) Bhi[4096) Blo[8192)
    const int tid = threadIdx.x;
    const int wid = tid >> 5, lane = tid & 31;
    const int g = lane >> 2, tg = lane & 3;
    const int wm = (wid & 3) * 16;
    const int wn = (wid >> 2) * 64;
    const int row0 = (bid >> 4) * 64;
    const int col0 = (bid & 15) * 128;

    const __nv_bfloat16* Asrc_h = g_Ahi + (size_t)row0 * 1024;
    const __nv_bfloat16* Asrc_l = g_Alo + (size_t)row0 * 1024;
    const __nv_bfloat16* Bsrc_h = g_Bhi + (size_t)col0 * 1024;
    const __nv_bfloat16* Bsrc_l = g_Blo + (size_t)col0 * 1024;

    float acc[8][4];
#pragma unroll
    for (int nt = 0; nt < 8; nt++)
#pragma unroll
        for (int q = 0; q < 4; q++) acc[nt][q] = 0.f;

    auto load_stage = [&](int s, int kt) {
#pragma unroll
        for (int q = 0; q < 3; q++) {
            int idx = tid + q * 256;          // 0..767
            const __nv_bfloat16* src;
            uint32_t arr_off;
            int rc;
            if (idx < 256) {
                rc = idx & 127;
                src = (idx < 128) ? Asrc_h : Asrc_l;
                arr_off = (idx < 128) ? 0 : 2048;
            } else {
                rc = (idx - 256) & 255;
                src = (idx < 512) ? Bsrc_h : Bsrc_l;
                arr_off = (idx < 512) ? 4096 : 8192;
            }
            int r = rc >> 1, c = rc & 1;
            uint32_t dst = smem_u32(sm) + s * 12288 + arr_off + r * 32 +
                           ((c * 16) ^ (((r >> 2) & 1) << 4));
            cp_async16(dst, src + (size_t)r * 1024 + kt * 16 + c * 8);
        }
        cp_commit();
    };

    uint32_t offA, offB[4];
    {
        int arow = ((lane >> 3) & 1) * 8 + (lane & 7);
        int cA = lane >> 4;
        int brow = ((lane >> 4) << 3) + (lane & 7);
        int cB = (lane >> 3) & 1;
        int rA = wm + arow;
        offA = rA * 32 + ((cA ^ ((rA >> 2) & 1)) << 4);
#pragma unroll
        for (int p = 0; p < 4; p++) {
            int r = wn + p * 16 + brow;
            offB[p] = r * 32 + ((cB ^ ((r >> 2) & 1)) << 4);
        }
    }

    load_stage(0, 0);
    load_stage(1, 1);

    int sread = 0;
    for (int kt = 0; kt < 64; kt++) {
        if (kt < 63) cp_wait<1>(); else cp_wait<0>();
        __syncthreads();
        if (kt + 2 < 64) {
            int sw = sread + 2; if (sw >= 3) sw -= 3;
            load_stage(sw, kt + 2);
        }

        const uint32_t base = smem_u32(sm) + sread * 12288;

        uint32_t ah[4], al[4], bh[4][4], bl[4][4];
        ldsm_x4(ah, base + offA);
        ldsm_x4(al, base + 2048 + offA);
#pragma unroll
        for (int p = 0; p < 4; p++) {
            ldsm_x4(bh[p], base + 4096 + offB[p]);
            ldsm_x4(bl[p], base + 8192 + offB[p]);
        }

        // pass-major ordering: 8 independent MMAs per group
#pragma unroll
        for (int nt = 0; nt < 8; nt++)
            mma16816(acc[nt], ah, &bh[nt >> 1][(nt & 1) * 2]);
#pragma unroll
        for (int nt = 0; nt < 8; nt++)
            mma16816(acc[nt], ah, &bl[nt >> 1][(nt & 1) * 2]);
#pragma unroll
        for (int nt = 0; nt < 8; nt++)
            mma16816(acc[nt], al, &bh[nt >> 1][(nt & 1) * 2]);

        sread = (sread + 1 == 3) ? 0 : sread + 1;
    }
#pragma unroll
    for (int nt = 0; nt < 8; nt++) {
        int r = row0 + wm + g;
        int c = col0 + wn + nt * 8 + tg * 2;
        *(float2*)&g_XM[(size_t)r * 2048 + c] =
            make_float2(acc[nt][0], acc[nt][1]);
        *(float2*)&g_XM[(size_t)(r + 8) * 2048 + c] =
            make_float2(acc[nt][2], acc[nt][3]);
    }
}

__device__ __forceinline__ void k3t_body(uint8_t* sm, int bid)
{
    // stage st at sm + st*16384: Xjh[0) Xjl[4096) XTh[8192) XTl[12288)
    // sInj at sm + 32768 (4 KB)
    float* sInj = (float*)(sm + 32768);

    const int tid  = threadIdx.x;
    const int lane = tid & 31, wid = tid >> 5;
    const int g = lane >> 2, tg = lane & 3;
    const int bc = bid >> 2;
    const int i0 = (bid & 3) * 256;
    const int b  = bc >> 4, ch = bc & 15;

    for (int q = tid; q < 1024; q += 256) sInj[q] = g_inorm[bc * 1024 + q];

    const int rw = i0 + wid * 32;
    const int ib0 = rw >> 4;

    uint32_t aih[2][4], ail[2][4];
    float nia[2], nib[2];
#pragma unroll
    for (int p = 0; p < 2; p++) {
        const int r = rw + 16 * p + g;
        const uint32_t* Xh = (const uint32_t*)(g_Xbfh + ((size_t)bc * 1024 + r) * 16);
        const uint32_t* Xl = (const uint32_t*)(g_Xbfl + ((size_t)bc * 1024 + r) * 16);
        aih[p][0] = Xh[tg];      aih[p][1] = Xh[64 + tg];
        aih[p][2] = Xh[tg + 4];  aih[p][3] = Xh[64 + tg + 4];
        ail[p][0] = Xl[tg];      ail[p][1] = Xl[64 + tg];
        ail[p][2] = Xl[tg + 4];  ail[p][3] = Xl[64 + tg + 4];
        nia[p] = g_inorm[bc * 1024 + r];
        nib[p] = g_inorm[bc * 1024 + r + 8];
    }

    float o[2][2][4];
#pragma unroll
    for (int p = 0; p < 2; p++)
#pragma unroll
        for (int u = 0; u < 2; u++)
#pragma unroll
            for (int q = 0; q < 4; q++) o[p][u][q] = 0.f;

    const int jr = ((lane >> 4) << 3) + (lane & 7);
    const int cS = (lane >> 3) & 1;
    const uint32_t offS = (uint32_t)(jr * 32 + ((cS ^ ((jr >> 2) & 1)) << 4));
    const int tl = jr;
    const int cbit = (lane >> 3) & 1;

    auto stage = [&](int st, int jt) {
        const size_t xb = ((size_t)bc * 1024 + jt * 128) * 32;   // bytes
        const size_t tb = ((size_t)bc * 16384 + jt * 128) * 2;   // bytes
        const char* srcs[4] = {(const char*)g_Xbfh + xb, (const char*)g_Xbfl + xb,
                               (const char*)g_XTh + tb,  (const char*)g_XTl + tb};
#pragma unroll
        for (int a = 0; a < 4; a++) {
            int q = tid;
            uint32_t dst;
            const char* src;
            if (a < 2) {
                int j = q >> 1, c = q & 1;
                dst = (uint32_t)(j * 32 + ((c ^ ((j >> 2) & 1)) << 4));
                src = srcs[a] + (size_t)j * 32 + c * 16;
            } else {
                int t = q >> 4, c = q & 15;
                dst = (uint32_t)(t * 256 + ((c ^ t) << 4));
                src = srcs[a] + (size_t)t * 2048 + c * 16;
            }
            cp_async16(smem_u32(sm) + st * 16384 + a * 4096 + dst, src);
        }
        cp_commit();
    };

    __syncthreads();            // sInj ready
    stage(0, 0);

    for (int jt = 0; jt < 8; jt++) {
        cp_wait<0>();
        __syncthreads();
        if (jt < 7) stage((jt + 1) & 1, jt + 1);

        const uint32_t sbase = smem_u32(sm) + (jt & 1) * 16384;

#pragma unroll 2
        for (int s2 = 0; s2 < 8; s2++) {
            const int js = s2 * 16;
            const int jabs = jt * 128 + js;
            const int jstep = jt * 8 + s2;

            uint32_t bh4[4], bl4[4];
            ldsm_x4(bh4, sbase + js * 32 + offS);
            ldsm_x4(bl4, sbase + 4096 + js * 32 + offS);
            const uint32_t cj = 2 * s2 + cbit;
            const uint32_t offP = (uint32_t)(tl * 256 + ((cj ^ tl) << 4));
            uint32_t th4[4], tl4[4];
            ldsm_x4(th4, sbase + 2 * 4096 + offP);
            ldsm_x4(tl4, sbase + 3 * 4096 + offP);

            float2 nj0 = *(const float2*)&sInj[jabs + 2 * tg];
            float2 nj1 = *(const float2*)&sInj[jabs + 8 + 2 * tg];

#pragma unroll
            for (int p = 0; p < 2; p++) {
                const float4* bp =
                    g_bperm + (((size_t)(ib0 + p) * 64 + jstep) * 32 + lane) * 2;
                float4 v0 = bp[0];
                float4 v1 = bp[1];

                float s0[4] = {0.f, 0.f, 0.f, 0.f};
                float s1[4] = {0.f, 0.f, 0.f, 0.f};
                mma16816(s0, aih[p], &bh4[0]); mma16816(s0, aih[p], &bl4[0]);
                mma16816(s0, ail[p], &bh4[0]);
                mma16816(s1, aih[p], &bh4[2]); mma16816(s1, aih[p], &bl4[2]);
                mma16816(s1, ail[p], &bh4[2]);

                float p00 = sig_tanh(v0.x * s0[0] * nia[p] * nj0.x);
                float p01 = sig_tanh(v0.y * s0[1] * nia[p] * nj0.y);
                float p02 = sig_tanh(v1.x * s0[2] * nib[p] * nj0.x);
                float p03 = sig_tanh(v1.y * s0[3] * nib[p] * nj0.y);
                float p10 = sig_tanh(v0.z * s1[0] * nia[p] * nj1.x);
                float p11 = sig_tanh(v0.w * s1[1] * nia[p] * nj1.y);
                float p12 = sig_tanh(v1.z * s1[2] * nib[p] * nj1.x);
                float p13 = sig_tanh(v1.w * s1[3] * nib[p] * nj1.y);

                uint32_t pah[4], pal[4];
                pah[0] = pack_bf16x2(p01, p00);
                pah[1] = pack_bf16x2(p03, p02);
                pah[2] = pack_bf16x2(p11, p10);
                pah[3] = pack_bf16x2(p13, p12);
                pal[0] = pack_bf16x2(p01 - bf16hi_f(pah[0]), p00 - bf16lo_f(pah[0]));
                pal[1] = pack_bf16x2(p03 - bf16hi_f(pah[1]), p02 - bf16lo_f(pah[1]));
                pal[2] = pack_bf16x2(p11 - bf16hi_f(pah[2]), p10 - bf16lo_f(pah[2]));
                pal[3] = pack_bf16x2(p13 - bf16hi_f(pah[3]), p12 - bf16lo_f(pah[3]));

                mma16816(o[p][0], pah, &th4[0]); mma16816(o[p][0], pah, &tl4[0]);
                mma16816(o[p][0], pal, &th4[0]);
                mma16816(o[p][1], pah, &th4[2]); mma16816(o[p][1], pah, &tl4[2]);
                mma16816(o[p][1], pal, &th4[2]);
            }
        }
    }

#pragma unroll
    for (int p = 0; p < 2; p++) {
        const int r = rw + 16 * p + g;
        float* base = g_cos + (((size_t)(b * 1024 + r) * 16) * 16) + ch;
        base[(2 * tg) * 16]            = o[p][0][0];
        base[(2 * tg + 1) * 16]        = o[p][0][1];
        base[2048 + (2 * tg) * 16]     = o[p][0][2];
        base[2048 + (2 * tg + 1) * 16] = o[p][0][3];
        base[(8 + 2 * tg) * 16]            = o[p][1][0];
        base[(8 + 2 * tg + 1) * 16]        = o[p][1][1];
        base[2048 + (8 + 2 * tg) * 16]     = o[p][1][2];
        base[2048 + (8 + 2 * tg + 1) * 16] = o[p][1][3];
    }
}

__global__ __launch_bounds__(256, 2) void k_heavy()
{
    __shared__ __align__(16) uint8_t sm[36864];
    if ((blockIdx.x & 1) == 0) k1_body(sm, blockIdx.x >> 1);
    else                       k3t_body(sm, blockIdx.x >> 1);
}

// =============================================================================
// K2: fold theta
// =============================================================================
__global__ __launch_bounds__(256) void k2_fold(const float* __restrict__ x,
                                               const float* __restrict__ theta,
                                               const float* __restrict__ bias)
{
    __shared__ float th[768];
    __shared__ float bs[16];
    const int tid = threadIdx.x;
    for (int q = tid; q < 768; q += 256) th[q] = theta[q];
    if (tid < 16) bs[tid] = bias[tid];
    __syncthreads();

    const int idx = blockIdx.x * 256 + tid;
    const int i   = idx & 1023;
    const int tau = (idx >> 10) & 15;
    const int b   = idx >> 14;

    const float* xr = x + (((b << 4) + tau) << 14) + (i << 4);
    float xrow[16];
#pragma unroll
    for (int q = 0; q < 4; q++)
        *(float4*)(xrow + 4 * q) = *(const float4*)(xr + 4 * q);

    float acc[16];
#pragma unroll
    for (int c = 0; c < 16; c++) acc[c] = bs[c];

    const int rbase = (b << 8) + (tau << 4);
#pragma unroll 4
    for (int tp = 0; tp < 16; ++tp) {
        const float* xm = g_XM + (size_t)(rbase + tp) * 2048 + i;
        float a0 = xrow[tp];
        float a1 = xm[0];
        float a2 = xm[1024];
        const float* t0 = th + tp * 48;
#pragma unroll
        for (int c = 0; c < 16; c++)
            acc[c] += a0 * t0[c] + a1 * t0[16 + c] + a2 * t0[32 + c];
    }

    float* dst = g_gc + ((size_t)b << 18) + (i << 8) + (tau << 4);
#pragma unroll
    for (int q = 0; q < 4; q++)
        *(float4*)(dst + 4 * q) = *(float4*)(acc + 4 * q);
}

// =============================================================================
// K4: fuse + channel softmax
// =============================================================================
__global__ __launch_bounds__(256) void k4_final(const float* __restrict__ x,
                                                float* __restrict__ out)
{
    const int idx = blockIdx.x * 256 + threadIdx.x;
    const int t = idx & 15;
    const int i = (idx >> 4) & 1023;
    const int b = idx >> 14;

    const float* gc = g_gc + (size_t)idx * 16;
    const float* cs = g_cos + (size_t)idx * 16;

    float g[16];
#pragma unroll
    for (int c = 0; c < 16; c++) {
        float xv = x[(((b << 4) + c) << 14) + (i << 4) + t];
        float r = gc[c] + xv;
        r = r > 0.f ? r : 0.f;
        g[c] = cs[c] * r;
    }
    float m = g[0];
#pragma unroll
    for (int c = 1; c < 16; c++) m = fmaxf(m, g[c]);
    float s = 0.f;
#pragma unroll
    for (int c = 0; c < 16; c++) {
        float e = __expf(g[c] - m);
        g[c] = e;
        s += e;
    }
    float rs = __fdividef(1.f, s);
#pragma unroll
    for (int c = 0; c < 16; c++)
        out[(((b << 4) + c) << 14) + (i << 4) + t] = g[c] * rs;
}

// =============================================================================
extern "C" void kernel_launch(void* const* d_in, const int* in_sizes, int n_in,
                              void* d_out, int out_size)
{
    const float* x     = (const float*)d_in[0];
    const float* beta  = (const float*)d_in[1];
    const float* theta = (const float*)d_in[2];
    const float* bias  = (const float*)d_in[3];
    const float* Lk    = (const float*)d_in[4];
    float* out = (float*)d_out;

    k_pre<<<2624, 256>>>(x, Lk, beta);
    k_heavy<<<512, 256>>>();
    k2_fold<<<256, 256>>>(x, theta, bias);
    k4_final<<<256, 256>>>(x, out);
}